// round 17
// baseline (speedup 1.0000x reference)
#include <cuda_runtime.h>

#define FULL_MASK 0xffffffffu
typedef unsigned long long u64;

// ---- f32x2 packed helpers (sm_103a FFMA2/FADD2 only reachable via PTX) ----
__device__ __forceinline__ u64 pk(float lo, float hi) {
    u64 r; asm("mov.b64 %0,{%1,%2};" : "=l"(r) : "f"(lo), "f"(hi)); return r;
}
__device__ __forceinline__ void up(u64 v, float& lo, float& hi) {
    asm("mov.b64 {%0,%1},%2;" : "=f"(lo), "=f"(hi) : "l"(v));
}
__device__ __forceinline__ u64 f2fma(u64 a, u64 b, u64 c) {
    u64 d; asm("fma.rn.f32x2 %0,%1,%2,%3;" : "=l"(d) : "l"(a), "l"(b), "l"(c)); return d;
}
__device__ __forceinline__ u64 f2mul(u64 a, u64 b) {
    u64 d; asm("mul.rn.f32x2 %0,%1,%2;" : "=l"(d) : "l"(a), "l"(b)); return d;
}
__device__ __forceinline__ u64 f2add(u64 a, u64 b) {
    u64 d; asm("add.rn.f32x2 %0,%1,%2;" : "=l"(d) : "l"(a), "l"(b)); return d;
}
__device__ __forceinline__ u64 swp(u64 v) {
    float a, b; up(v, a, b); return pk(b, a);
}

// packed complex multiply by broadcast scalar (yr,yi): dst = src * y  (split R/I)
__device__ __forceinline__ void cmulp(u64& Rd, u64& Id, u64 Rs, u64 Is,
                                      float yr, float yi) {
    u64 pyr = pk(yr, yr), pyi = pk(yi, yi), nyi = pk(-yi, -yi);
    Rd = f2fma(Rs, pyr, f2mul(Is, nyi));
    Id = f2fma(Rs, pyi, f2mul(Is, pyr));
}

// ---- compile-time CNOT-ring permutations & layout maps ----
__host__ __device__ constexpr int perm_apply(int r, int v) {
    for (int g = 0; g < 9; g++) {
        int t = g + r; if (t >= 9) t -= 9;
        v ^= ((v >> (8 - g)) & 1) << (8 - t);
    }
    return v;
}
__host__ __device__ constexpr int mask_bit(int t) {
    int m = 0;
    for (int b = 0; b < 9; b++)
        if ((perm_apply(3, 1 << b) >> t) & 1) m |= (1 << b);
    return m;
}
// Layout A: i = v (lane = v bits 0..4 = qubits 8..4; k = v bits 5..8 = qubits 3..0)
// Layout B: k' = v bits 1..4 (qubits 7..4); lane' = {v5,v6,v7,v0,v8} at bits {0..4}
__host__ __device__ constexpr int jB(int v) {
    int kp = (v >> 1) & 15;
    int lp = ((v >> 5) & 1) | (((v >> 6) & 1) << 1) | (((v >> 7) & 1) << 2)
           | ((v & 1) << 3) | (((v >> 8) & 1) << 4);
    return (kp << 5) | lp;
}
__host__ __device__ constexpr int vB(int kp, int ln) {   // inverse of jB
    return ((ln >> 3) & 1) | (kp << 1) | ((ln & 1) << 5)
         | (((ln >> 1) & 1) << 6) | (((ln >> 2) & 1) << 7) | (((ln >> 4) & 1) << 8);
}
// destination float2-address for dest-index j:
//   pair slot = lane*8 + (p ^ (lane&7)), p = k bits 3..1; half = k bit 0
__host__ __device__ constexpr int dstA(int j) {
    int lane = j & 31, p = (j >> 6) & 7, half = (j >> 5) & 1;
    return (lane * 8 + (p ^ (lane & 7))) * 2 + half;
}
// measurement constants for layout B (acc[w] uses t = 8-w)
__host__ __device__ constexpr int kidx_w(int w) { return (mask_bit(8 - w) >> 1) & 15; }
__host__ __device__ constexpr int lmk_w(int w) {
    int mk = mask_bit(8 - w);
    return ((mk >> 5) & 1) | (((mk >> 6) & 1) << 1) | (((mk >> 7) & 1) << 2)
         | ((mk & 1) << 3) | (((mk >> 8) & 1) << 4);
}

// ---- native-layout RY gates: amp k = V[k] = (re, im); real coeffs act componentwise ----
template <int PB>
__device__ __forceinline__ void ry16(u64 (&V)[16], float c, float s) {
    const u64 pc = pk(c, c), ps = pk(s, s), ns = pk(-s, -s);
    const int d = 1 << PB;
#pragma unroll
    for (int t = 0; t < 8; t++) {
        const int q = ((t >> PB) << (PB + 1)) | (t & (d - 1));
        const int j = q | d;
        u64 a = V[q], b = V[j];
        V[q] = f2fma(pc, a, f2mul(ns, b));
        V[j] = f2fma(ps, a, f2mul(pc, b));
    }
}
template <int P>
__device__ __forceinline__ void ry16_cross(u64 (&V)[16], float c, float s, int lane) {
    const int msk = 1 << P;
    const float sp = (lane & msk) ? s : -s;
    const u64 pc = pk(c, c), psl = pk(sp, sp);
#pragma unroll
    for (int k = 0; k < 16; k++) {
        u64 sh = __shfl_xor_sync(FULL_MASK, V[k], msk);
        V[k] = f2fma(pc, V[k], f2mul(psl, sh));
    }
}
// diag: per-amp float4 (cr, cr, -ci, ci); both halves are aligned pairs
__device__ __forceinline__ void diag16(u64 (&V)[16], const float4* T, int lane) {
#pragma unroll
    for (int k = 0; k < 16; k++) {
        float4 t = T[k * 32 + lane];
        u64 ccc = pk(t.x, t.y);
        u64 cnc = pk(t.z, t.w);
        V[k] = f2fma(V[k], ccc, f2mul(swp(V[k]), cnc));
    }
}
// table scatter (ushort4: dests for k=4p2..4p2+3) + deterministic LDS.128 gather
__device__ __forceinline__ void scat_gath16(u64 (&V)[16], float4* buf4,
                                            const ushort4* tbl, int lane) {
    float2* buf2 = (float2*)buf4;
    __syncwarp();
#pragma unroll
    for (int p2 = 0; p2 < 4; p2++) {
        ushort4 t = tbl[p2 * 32 + lane];
        *(u64*)&buf2[t.x] = V[4 * p2 + 0];
        *(u64*)&buf2[t.y] = V[4 * p2 + 1];
        *(u64*)&buf2[t.z] = V[4 * p2 + 2];
        *(u64*)&buf2[t.w] = V[4 * p2 + 3];
    }
    __syncwarp();
#pragma unroll
    for (int p = 0; p < 8; p++) {
        float4 q = buf4[lane * 8 + (p ^ (lane & 7))];
        V[2 * p]     = pk(q.x, q.y);
        V[2 * p + 1] = pk(q.z, q.w);
    }
}

__global__ void __launch_bounds__(256)
qsim_kernel(const float* __restrict__ x, const float* __restrict__ wt,
            float* __restrict__ out, int B) {
    __shared__ float2 s_m00[9], s_m01[9];        // layer-0 Rot (for init fold)
    __shared__ float2 s_ry[18];                  // (c, s) layers 1,2
    __shared__ float2 s_ph[3][9];                // e^{-i ang/2}: phi1, omega1, phi2
    __shared__ ushort4 s_tC0[128];               // C0 scatter dests (A layout)
    __shared__ ushort4 s_tAB[128];               // A->B transpose dests
    __shared__ ushort4 s_tC1B[128];              // C1 dests from B positions
    __shared__ float4 s_T14[512];                // D1(layer1), layout A, (cr,cr,-ci,ci)
    __shared__ float4 s_TE4[512];                // D2(l1)*C1-conj(D1(l2)), layout B
    __shared__ float4 s_buf[8][256];             // per-warp pair buffer (32KB)

    const int tid = threadIdx.x;

    // ---- per-layer gate data ----
    if (tid < 27) {
        const int l = tid / 9, w = tid % 9;
        const float* p = wt + tid * 3;
        float phi = p[0], th = p[1], om = p[2];
        float c, s;
        __sincosf(0.5f * th, &s, &c);
        if (l == 0) {
            float a  = 0.5f * (phi + om);
            float bb = 0.5f * (phi - om);
            float ca, sa, cb, sb;
            __sincosf(a, &sa, &ca);
            __sincosf(bb, &sb, &cb);
            s_m00[w] = make_float2(c * ca, -c * sa);
            s_m01[w] = make_float2(-s * cb, -s * sb);
        } else {
            s_ry[(l - 1) * 9 + w] = make_float2(c, s);
            float cp, sp;
            __sincosf(0.5f * phi, &sp, &cp);
            if (l == 1) {
                s_ph[0][w] = make_float2(cp, -sp);
                float co, so;
                __sincosf(0.5f * om, &so, &co);
                s_ph[1][w] = make_float2(co, -so);
            } else {
                s_ph[2][w] = make_float2(cp, -sp);
            }
        }
    }
    // ---- scatter tables (ushort4 per (p2, lane): dests for k = 4p2..4p2+3) ----
    for (int e = tid; e < 128; e += blockDim.x) {
        int p2 = e >> 5, ln = e & 31;
        unsigned short d[3][4];
#pragma unroll
        for (int m = 0; m < 4; m++) {
            int k = 4 * p2 + m;
            int v = k * 32 + ln;                       // source amp (reg layout)
            d[0][m] = (unsigned short)dstA(perm_apply(1, v));   // C0
            d[1][m] = (unsigned short)dstA(jB(v));              // A->B
            int vb = vB(k, ln);                        // source amp in layout B
            d[2][m] = (unsigned short)dstA(perm_apply(2, vb));  // C1 (B -> A)
        }
        s_tC0[e]  = make_ushort4(d[0][0], d[0][1], d[0][2], d[0][3]);
        s_tAB[e]  = make_ushort4(d[1][0], d[1][1], d[1][2], d[1][3]);
        s_tC1B[e] = make_ushort4(d[2][0], d[2][1], d[2][2], d[2][3]);
    }
    __syncthreads();

    // ---- build diagonal tables (weights-only; once per block) ----
    for (int i = tid; i < 512; i += blockDim.x) {
        float t1r = 1.0f, t1i = 0.0f, ter = 1.0f, tei = 0.0f;
        int ci = perm_apply(2, i);
#pragma unroll
        for (int w = 0; w < 9; w++) {
            int b0 = (i >> (8 - w)) & 1;
            int b1 = (ci >> (8 - w)) & 1;
            float2 p0 = s_ph[0][w];
            float y0 = b0 ? -p0.y : p0.y;
            float nr = t1r * p0.x - t1i * y0;
            t1i = t1r * y0 + t1i * p0.x; t1r = nr;
            float2 p1 = s_ph[1][w];
            float y1 = b0 ? -p1.y : p1.y;
            nr = ter * p1.x - tei * y1;
            tei = ter * y1 + tei * p1.x; ter = nr;
            float2 p2 = s_ph[2][w];
            float y2 = b1 ? -p2.y : p2.y;
            nr = ter * p2.x - tei * y2;
            tei = ter * y2 + tei * p2.x; ter = nr;
        }
        s_T14[i] = make_float4(t1r, t1r, -t1i, t1i);          // layout A slot = i
        s_TE4[jB(i)] = make_float4(ter, ter, -tei, tei);      // layout B slot
    }
    __syncthreads();

    const int lane = tid & 31;
    const int warp = tid >> 5;
    float4* buf4 = s_buf[warp];
    float2* buf2 = (float2*)buf4;
    const int gw = blockIdx.x * (blockDim.x >> 5) + warp;
    const int nw = gridDim.x * (blockDim.x >> 5);

    // measurement constants (lane-only; hoisted out of the batch loop)
    constexpr int KW[9] = { kidx_w(0), kidx_w(1), kidx_w(2), kidx_w(3),
                            kidx_w(4), kidx_w(5), kidx_w(6), kidx_w(7), kidx_w(8) };
    constexpr int LW[9] = { lmk_w(0), lmk_w(1), lmk_w(2), lmk_w(3),
                            lmk_w(4), lmk_w(5), lmk_w(6), lmk_w(7), lmk_w(8) };
    float sg[9];
#pragma unroll
    for (int w = 0; w < 9; w++)
        sg[w] = (__popc(lane & LW[w]) & 1) ? -1.0f : 1.0f;

    for (int b = gw; b < B; b += nw) {
        // ---- per-qubit angles ----
        float cs[9], sn[9];
#pragma unroll
        for (int w = 0; w < 9; w++) {
            float h2 = 0.5f * __ldg(&x[b * 9 + w]);
            __sincosf(h2, &sn[w], &cs[w]);
        }

        // ---- layer-0 rotations folded into per-qubit 2-vectors ----
        float Lr = 1.0f, Li = 0.0f;
#pragma unroll
        for (int p = 0; p < 5; p++) {
            int w = 8 - p;
            float2 m0 = s_m00[w], m1 = s_m01[w];
            float c = cs[w], s = sn[w];
            float vr, vi;
            if ((lane >> p) & 1) { vr = -m1.x * c - m0.y * s; vi = m1.y * c - m0.x * s; }
            else                 { vr =  m0.x * c + m1.y * s; vi = m0.y * c - m1.x * s; }
            float nr = Lr * vr - Li * vi;
            Li = Lr * vi + Li * vr;
            Lr = nr;
        }
        float awr[4], awi[4], bwr[4], bwi[4];
#pragma unroll
        for (int w = 0; w < 4; w++) {
            float2 m0 = s_m00[w], m1 = s_m01[w];
            float c = cs[w], s = sn[w];
            awr[w] =  m0.x * c + m1.y * s;  awi[w] = m0.y * c - m1.x * s;
            bwr[w] = -m1.x * c - m0.y * s;  bwi[w] = m1.y * c - m0.x * s;
        }
        float A0r = awr[0] * Lr - awi[0] * Li, A0i = awr[0] * Li + awi[0] * Lr;
        float B0r = bwr[0] * Lr - bwi[0] * Li, B0i = bwr[0] * Li + bwi[0] * Lr;

        // ---- build state by packed doubling over k bits (split R/I packs) ----
        u64 R[8], I[8];
        R[0] = pk(awr[3], bwr[3]); I[0] = pk(awi[3], bwi[3]);
        cmulp(R[1], I[1], R[0], I[0], bwr[2], bwi[2]);
        cmulp(R[0], I[0], R[0], I[0], awr[2], awi[2]);
        cmulp(R[2], I[2], R[0], I[0], bwr[1], bwi[1]);
        cmulp(R[3], I[3], R[1], I[1], bwr[1], bwi[1]);
        cmulp(R[0], I[0], R[0], I[0], awr[1], awi[1]);
        cmulp(R[1], I[1], R[1], I[1], awr[1], awi[1]);
#pragma unroll
        for (int p = 0; p < 4; p++)
            cmulp(R[p + 4], I[p + 4], R[p], I[p], B0r, B0i);
#pragma unroll
        for (int p = 0; p < 4; p++)
            cmulp(R[p], I[p], R[p], I[p], A0r, A0i);

        // ---- C0 permutation: scatter split packs, gather native paired amps ----
        u64 V[16];
        {
            __syncwarp();
#pragma unroll
            for (int p2 = 0; p2 < 4; p2++) {
                ushort4 t = s_tC0[p2 * 32 + lane];
                float r0, r1, i0f, i1f, r2, r3, i2f, i3f;
                up(R[2 * p2], r0, r1);     up(I[2 * p2], i0f, i1f);
                up(R[2 * p2 + 1], r2, r3); up(I[2 * p2 + 1], i2f, i3f);
                buf2[t.x] = make_float2(r0, i0f);
                buf2[t.y] = make_float2(r1, i1f);
                buf2[t.z] = make_float2(r2, i2f);
                buf2[t.w] = make_float2(r3, i3f);
            }
            __syncwarp();
#pragma unroll
            for (int p = 0; p < 8; p++) {
                float4 q = buf4[lane * 8 + (p ^ (lane & 7))];
                V[2 * p]     = pk(q.x, q.y);
                V[2 * p + 1] = pk(q.z, q.w);
            }
        }

        // ---- D1(layer1) diag (A) ----
        diag16(V, s_T14, lane);

        // ---- layer 1, A-phase gates: qubits 0..3 (k bits 3..0) ----
        ry16<3>(V, s_ry[0].x, s_ry[0].y);
        ry16<2>(V, s_ry[1].x, s_ry[1].y);
        ry16<1>(V, s_ry[2].x, s_ry[2].y);
        ry16<0>(V, s_ry[3].x, s_ry[3].y);

        // ---- transpose A -> B ----
        scat_gath16(V, buf4, s_tAB, lane);

        // ---- layer 1, B-phase: qubits 4..7 (k' bits 3..0) + qubit 8 cross ----
        ry16<3>(V, s_ry[4].x, s_ry[4].y);
        ry16<2>(V, s_ry[5].x, s_ry[5].y);
        ry16<1>(V, s_ry[6].x, s_ry[6].y);
        ry16<0>(V, s_ry[7].x, s_ry[7].y);
        ry16_cross<3>(V, s_ry[8].x, s_ry[8].y, lane);

        // ---- E diag (B) ----
        diag16(V, s_TE4, lane);

        // ---- C1 permutation composed with B -> A transpose ----
        scat_gath16(V, buf4, s_tC1B, lane);

        // ---- layer 2, A-phase gates ----
        ry16<3>(V, s_ry[9].x,  s_ry[9].y);
        ry16<2>(V, s_ry[10].x, s_ry[10].y);
        ry16<1>(V, s_ry[11].x, s_ry[11].y);
        ry16<0>(V, s_ry[12].x, s_ry[12].y);

        // ---- transpose A -> B ----
        scat_gath16(V, buf4, s_tAB, lane);

        // ---- layer 2, B-phase gates ----
        ry16<3>(V, s_ry[13].x, s_ry[13].y);
        ry16<2>(V, s_ry[14].x, s_ry[14].y);
        ry16<1>(V, s_ry[15].x, s_ry[15].y);
        ry16<0>(V, s_ry[16].x, s_ry[16].y);
        ry16_cross<3>(V, s_ry[17].x, s_ry[17].y, lane);

        // ---- measurement in layout B (final CNOT folded as parity masks) ----
        u64 M[16];
        const u64 NEG1 = pk(-1.0f, -1.0f);
#pragma unroll
        for (int k = 0; k < 16; k++)
            M[k] = f2mul(V[k], V[k]);                  // (re^2, im^2)
        // full packed WHT over the 4 k'-bits (componentwise; linear)
#pragma unroll
        for (int j = 0; j < 4; j++) {
            const int d = 1 << j;
#pragma unroll
            for (int t = 0; t < 8; t++) {
                const int q = ((t >> j) << (j + 1)) | (t & (d - 1));
                const int v = q | d;
                u64 a = M[q], bb = M[v];
                M[q] = f2add(a, bb);
                M[v] = f2fma(bb, NEG1, a);
            }
        }
        float acc[9];
#pragma unroll
        for (int w = 0; w < 9; w++) {
            float lo, hi; up(M[KW[w]], lo, hi);
            acc[w] = (lo + hi) * sg[w];
        }
        // packed warp reduction
        u64 ac[4];
#pragma unroll
        for (int j = 0; j < 4; j++) ac[j] = pk(acc[2 * j], acc[2 * j + 1]);
        float a8 = acc[8];
#pragma unroll
        for (int off = 16; off > 0; off >>= 1) {
#pragma unroll
            for (int j = 0; j < 4; j++)
                ac[j] = f2add(ac[j], __shfl_xor_sync(FULL_MASK, ac[j], off));
            a8 += __shfl_xor_sync(FULL_MASK, a8, off);
        }
        if (lane == 0) {
#pragma unroll
            for (int j = 0; j < 4; j++) {
                float lo, hi; up(ac[j], lo, hi);
                out[b * 9 + 2 * j]     = lo;
                out[b * 9 + 2 * j + 1] = hi;
            }
            out[b * 9 + 8] = a8;
        }
    }
}

extern "C" void kernel_launch(void* const* d_in, const int* in_sizes, int n_in,
                              void* d_out, int out_size) {
    const float* x  = (const float*)d_in[0];   // (32768, 9) fp32
    const float* wt = (const float*)d_in[1];   // (3, 9, 3) fp32
    float* out = (float*)d_out;                // (32768, 9) fp32
    int B = in_sizes[0] / 9;
    qsim_kernel<<<2048, 256>>>(x, wt, out, B);
}